// round 1
// baseline (speedup 1.0000x reference)
#include <cuda_runtime.h>
#include <stdint.h>
#include <math.h>

#define N_NODES 100000
#define N_PAD   100096        // multiple of 128 for tile padding
#define DIM     64
#define HID     256
#define BN_EPS  1e-5f

// ---------------- scratch (static device globals; no allocation) ----------------
__device__ int   g_deg[N_PAD];
__device__ int   g_rowstart[N_PAD];
__device__ int   g_cursor[N_PAD];
__device__ int   g_csr[1600000];
__device__ int   g_total;
__device__ float g_x [(size_t)N_PAD * DIM];   // combined agg/deg + h
__device__ float g_x1[(size_t)N_PAD * HID];   // hidden activations
__device__ float g_colsum[DIM];
__device__ float g_colsq [DIM];
__device__ __align__(16) float g_scale[DIM];
__device__ __align__(16) float g_shift[DIM];

// ---------------- packed f32x2 helpers (sm_10x FFMA2) ----------------
__device__ __forceinline__ void fma2(unsigned long long &d, unsigned long long a,
                                     unsigned long long b) {
    asm("fma.rn.f32x2 %0, %1, %2, %0;" : "+l"(d) : "l"(a), "l"(b));
}
__device__ __forceinline__ unsigned long long pack2(float lo, float hi) {
    unsigned long long r;
    asm("mov.b64 %0, {%1,%2};" : "=l"(r) : "f"(lo), "f"(hi));
    return r;
}
__device__ __forceinline__ void unpack2(unsigned long long v, float &lo, float &hi) {
    asm("mov.b64 {%0,%1}, %2;" : "=f"(lo), "=f"(hi) : "l"(v));
}

// ---------------- kernels ----------------
__global__ void k_zero() {
    int i = blockIdx.x * blockDim.x + threadIdx.x;
    if (i < N_PAD) g_deg[i] = 0;
    if (i < DIM) { g_colsum[i] = 0.f; g_colsq[i] = 0.f; }
    if (i == 0) g_total = 0;
    const int padN = N_PAD - N_NODES;           // 96
    if (i < padN * DIM) g_x [(size_t)N_NODES * DIM + i] = 0.f;
    if (i < padN * HID) g_x1[(size_t)N_NODES * HID + i] = 0.f;
}

__global__ void k_hist(const int* __restrict__ dst, int E) {
    int i = blockIdx.x * blockDim.x + threadIdx.x;
    if (i < E) atomicAdd(&g_deg[dst[i]], 1);
}

// one-kernel exclusive scan: block-local Hillis-Steele + atomic base allocation.
// (row ordering in CSR memory is allocation-order; consistent rowstart/cursor.)
__global__ void k_scan() {
    __shared__ int s[256];
    __shared__ int sbase;
    int t = threadIdx.x;
    int i = blockIdx.x * 256 + t;
    int d = (i < N_NODES) ? g_deg[i] : 0;
    s[t] = d;
    __syncthreads();
    for (int off = 1; off < 256; off <<= 1) {
        int v = (t >= off) ? s[t - off] : 0;
        __syncthreads();
        s[t] += v;
        __syncthreads();
    }
    if (t == 255) sbase = atomicAdd(&g_total, s[255]);
    __syncthreads();
    if (i < N_NODES) {
        int start = sbase + s[t] - d;   // exclusive
        g_rowstart[i] = start;
        g_cursor[i]   = start;
    }
}

__global__ void k_fill(const int* __restrict__ src, const int* __restrict__ dst, int E) {
    int i = blockIdx.x * blockDim.x + threadIdx.x;
    if (i < E) {
        int d = dst[i];
        int pos = atomicAdd(&g_cursor[d], 1);
        g_csr[pos] = src[i];
    }
}

// warp-per-node gather: x[n] = segsum(h[src])/max(deg,1) + h[n]
__global__ void k_agg(const float* __restrict__ h) {
    int warp = (blockIdx.x * blockDim.x + threadIdx.x) >> 5;
    int lane = threadIdx.x & 31;
    if (warp >= N_NODES) return;
    int start = g_rowstart[warp];
    int deg   = g_deg[warp];
    float a0 = 0.f, a1 = 0.f;
    for (int j = 0; j < deg; ++j) {
        int s = g_csr[start + j];
        const float* hp = h + (size_t)s * DIM;
        a0 += hp[lane];
        a1 += hp[lane + 32];
    }
    float inv = 1.f / fmaxf((float)deg, 1.f);
    const float* hn = h + (size_t)warp * DIM;
    g_x[(size_t)warp * DIM + lane]      = fmaf(a0, inv, hn[lane]);
    g_x[(size_t)warp * DIM + lane + 32] = fmaf(a1, inv, hn[lane + 32]);
}

// GEMM1: x1 = relu(x @ W1 + b1).  A[100k,64] B[64,256].
// block 256 thr, M_TILE=64. thread = 4 nodes x 16 cols (8 col-pairs, f32x2).
#define SMEM1_FLOATS (64*256 + 64*68)
__global__ void __launch_bounds__(256, 2)
k_gemm1(const float* __restrict__ W1, const float* __restrict__ b1) {
    extern __shared__ float sm[];
    float* sW = sm;              // [64][256]
    float* sA = sm + 64 * 256;   // [64][68] (pad for banks)
    const int t  = threadIdx.x;
    const int m0 = blockIdx.x * 64;

    {   // stage W1 (64KB) and A tile
        float4* dW = (float4*)sW;
        const float4* srcW = (const float4*)W1;
        #pragma unroll
        for (int i = t; i < 64 * 256 / 4; i += 256) dW[i] = srcW[i];
        for (int i = t; i < 64 * 16; i += 256) {
            int m = i >> 4, c4 = i & 15;
            float4 v = *(const float4*)&g_x[(size_t)(m0 + m) * DIM + c4 * 4];
            *(float4*)&sA[m * 68 + c4 * 4] = v;
        }
    }
    __syncthreads();

    const int tx = t & 15, ty = t >> 4;
    unsigned long long acc[4][8];
    #pragma unroll
    for (int i = 0; i < 4; ++i)
        #pragma unroll
        for (int j = 0; j < 8; ++j) acc[i][j] = 0ull;

    #pragma unroll 4
    for (int k = 0; k < 64; ++k) {
        unsigned long long bb[8];
        #pragma unroll
        for (int j = 0; j < 8; ++j)
            bb[j] = *(const unsigned long long*)&sW[k * 256 + 2 * tx + 32 * j];
        #pragma unroll
        for (int i = 0; i < 4; ++i) {
            float a = sA[(ty * 4 + i) * 68 + k];
            unsigned long long a2 = pack2(a, a);
            #pragma unroll
            for (int j = 0; j < 8; ++j) fma2(acc[i][j], a2, bb[j]);
        }
    }

    #pragma unroll
    for (int i = 0; i < 4; ++i) {
        int m = m0 + ty * 4 + i;
        if (m >= N_NODES) continue;
        #pragma unroll
        for (int j = 0; j < 8; ++j) {
            int c = 2 * tx + 32 * j;
            float lo, hi;
            unpack2(acc[i][j], lo, hi);
            lo = fmaxf(lo + b1[c], 0.f);
            hi = fmaxf(hi + b1[c + 1], 0.f);
            *(float2*)&g_x1[(size_t)m * HID + c] = make_float2(lo, hi);
        }
    }
}

// GEMM2: out_preBN = relu(x1 @ W2 + b2), plus per-column sum / sumsq.
// block 256 thr, M_TILE=128. thread = 8 nodes (4 node-pairs, f32x2) x 4 cols.
// A chunk staged transposed sT[k][m] so node pairs are one LDS.64.
#define SMEM2_FLOATS (256*64 + 64*130)
__global__ void __launch_bounds__(256, 2)
k_gemm2(const float* __restrict__ W2, const float* __restrict__ bias2,
        float* __restrict__ out) {
    extern __shared__ float sm[];
    float* sW = sm;              // [256][64]
    float* sT = sm + 256 * 64;   // [64][130] transposed chunk
    const int t  = threadIdx.x;
    const int m0 = blockIdx.x * 128;
    const int tx = t & 15, ty = t >> 4;

    {
        float4* dW = (float4*)sW;
        const float4* srcW = (const float4*)W2;
        #pragma unroll
        for (int i = t; i < 256 * 64 / 4; i += 256) dW[i] = srcW[i];
    }

    unsigned long long acc[4][4];   // [node-pair p][col j]
    #pragma unroll
    for (int p = 0; p < 4; ++p)
        #pragma unroll
        for (int j = 0; j < 4; ++j) acc[p][j] = 0ull;

    for (int kk = 0; kk < 4; ++kk) {
        __syncthreads();
        for (int i = t; i < 128 * 16; i += 256) {
            int m = i >> 4, k4 = i & 15;
            float4 v = *(const float4*)&g_x1[(size_t)(m0 + m) * HID + kk * 64 + k4 * 4];
            sT[(k4 * 4 + 0) * 130 + m] = v.x;
            sT[(k4 * 4 + 1) * 130 + m] = v.y;
            sT[(k4 * 4 + 2) * 130 + m] = v.z;
            sT[(k4 * 4 + 3) * 130 + m] = v.w;
        }
        __syncthreads();

        #pragma unroll 4
        for (int k = 0; k < 64; ++k) {
            unsigned long long a2[4];
            #pragma unroll
            for (int p = 0; p < 4; ++p)
                a2[p] = *(const unsigned long long*)&sT[k * 130 + ty * 8 + 2 * p];
            #pragma unroll
            for (int j = 0; j < 4; ++j) {
                float b = sW[(kk * 64 + k) * 64 + tx + 16 * j];
                unsigned long long b2p = pack2(b, b);
                #pragma unroll
                for (int p = 0; p < 4; ++p) fma2(acc[p][j], a2[p], b2p);
            }
        }
    }

    __syncthreads();   // done with sT as A; reuse for BN reduction

    float csum[4] = {0.f, 0.f, 0.f, 0.f};
    float csq [4] = {0.f, 0.f, 0.f, 0.f};
    #pragma unroll
    for (int p = 0; p < 4; ++p) {
        int mA = m0 + ty * 8 + 2 * p;
        int mB = mA + 1;
        #pragma unroll
        for (int j = 0; j < 4; ++j) {
            int c = tx + 16 * j;
            float lo, hi;
            unpack2(acc[p][j], lo, hi);
            float bv = bias2[c];
            lo = fmaxf(lo + bv, 0.f);
            hi = fmaxf(hi + bv, 0.f);
            if (mA < N_NODES) {
                out[(size_t)mA * DIM + c] = lo;
                csum[j] += lo; csq[j] += lo * lo;
            }
            if (mB < N_NODES) {
                out[(size_t)mB * DIM + c] = hi;
                csum[j] += hi; csq[j] += hi * hi;
            }
        }
    }
    #pragma unroll
    for (int j = 0; j < 4; ++j) {
        int c = tx + 16 * j;
        sT[c * 16 + ty]        = csum[j];
        sT[1024 + c * 16 + ty] = csq[j];
    }
    __syncthreads();
    if (t < DIM) {
        float s = 0.f, q = 0.f;
        #pragma unroll
        for (int u = 0; u < 16; ++u) {
            s += sT[t * 16 + u];
            q += sT[1024 + t * 16 + u];
        }
        atomicAdd(&g_colsum[t], s);
        atomicAdd(&g_colsq[t],  q);
    }
}

__global__ void k_bnstats(const float* __restrict__ gamma, const float* __restrict__ beta) {
    int t = threadIdx.x;
    const float invN = 1.f / (float)N_NODES;
    float mean = g_colsum[t] * invN;
    float var  = g_colsq[t] * invN - mean * mean;
    float sc   = gamma[t] * rsqrtf(var + BN_EPS);
    g_scale[t] = sc;
    g_shift[t] = fmaf(-mean, sc, beta[t]);
}

__global__ void k_bnapply(float* __restrict__ out) {
    int i = blockIdx.x * blockDim.x + threadIdx.x;   // float4 index
    if (i < N_NODES * (DIM / 4)) {
        int c4 = i & 15;
        float4 v  = ((float4*)out)[i];
        float4 sc = ((const float4*)g_scale)[c4];
        float4 sh = ((const float4*)g_shift)[c4];
        v.x = fmaf(v.x, sc.x, sh.x);
        v.y = fmaf(v.y, sc.y, sh.y);
        v.z = fmaf(v.z, sc.z, sh.z);
        v.w = fmaf(v.w, sc.w, sh.w);
        ((float4*)out)[i] = v;
    }
}

// ---------------- launch ----------------
extern "C" void kernel_launch(void* const* d_in, const int* in_sizes, int n_in,
                              void* d_out, int out_size) {
    const float* h     = (const float*)d_in[0];
    const float* W1    = (const float*)d_in[1];
    const float* b1    = (const float*)d_in[2];
    const float* W2    = (const float*)d_in[3];
    const float* b2    = (const float*)d_in[4];
    const float* gamma = (const float*)d_in[5];
    const float* beta  = (const float*)d_in[6];
    const int*   src   = (const int*)d_in[7];
    const int*   dst   = (const int*)d_in[8];
    const int    E     = in_sizes[7];
    float* out = (float*)d_out;

    cudaFuncSetAttribute(k_gemm1, cudaFuncAttributeMaxDynamicSharedMemorySize,
                         SMEM1_FLOATS * (int)sizeof(float));
    cudaFuncSetAttribute(k_gemm2, cudaFuncAttributeMaxDynamicSharedMemorySize,
                         SMEM2_FLOATS * (int)sizeof(float));

    const int eb = (E + 255) / 256;
    k_zero<<<(N_PAD + 255) / 256, 256>>>();
    k_hist<<<eb, 256>>>(dst, E);
    k_scan<<<(N_NODES + 255) / 256, 256>>>();
    k_fill<<<eb, 256>>>(src, dst, E);
    k_agg<<<(N_NODES * 32 + 255) / 256, 256>>>(h);
    k_gemm1<<<(N_NODES + 63) / 64, 256, SMEM1_FLOATS * sizeof(float)>>>(W1, b1);
    k_gemm2<<<(N_NODES + 127) / 128, 256, SMEM2_FLOATS * sizeof(float)>>>(W2, b2, out);
    k_bnstats<<<1, DIM>>>(gamma, beta);
    k_bnapply<<<(N_NODES * (DIM / 4) + 255) / 256, 256>>>(out);
}